// round 17
// baseline (speedup 1.0000x reference)
#include <cuda_runtime.h>
#include <cuda_bf16.h>

#define BATCH 16
#define MP 30      // max people
#define NJ 17      // joints
#define AD 17      // ae tag dim
#define RES 512
#define RR (RES*RES)

#define JPI (MP * NJ)                    // 510 joints per image
#define NPT (BATCH * MP)                 // 480 persons total
#define CPI 32                           // CTAs per image (32*16 warps >= 510 joints)
#define NPAIR 435                        // MP*(MP-1)/2 unordered pairs

// person-level accumulators (zero-init; finalizer re-zeroes each replay)
__device__ float g_psum[NPT * AD];       // per-(person,d) masked tag sums
__device__ float g_sqp [NPT];            // per-person sum of 2D*s2-2*s1^2
__device__ float g_cnt [NPT];            // per-person valid joint count
__device__ unsigned g_done[BATCH];       // per-image CTA arrival counters

__global__ __launch_bounds__(512, 1)
void ae_fused_kernel(const float* __restrict__ tags,
                     const int*   __restrict__ joints,
                     float*       __restrict__ out)
{
    const unsigned FULL = 0xffffffffu;
    const int tid  = threadIdx.x;
    const int lane = tid & 31;
    const int b    = blockIdx.x / CPI;               // image
    const int ci   = blockIdx.x % CPI;               // CTA within image

    // ---------------- Phase A: gather, one joint per warp ------------------
    {
        const int jl = ci * 16 + (tid >> 5);         // joint within image [0,512)
        if (jl < JPI) {
            const int jj = b * JPI + jl;             // global joint id
            const int pt = jj / NJ;                  // global person id

            const int2 jt = __ldg((const int2*)joints + jj);   // {idx, vis}

            if (jt.y > 0) {
                int off = jt.x % RR;
                if (off < 0) off += RR;
                const int x = off % RES;             // first spatial axis (torch)
                const int y = off / RES;

                float v = 0.0f;
                if (lane < AD)
                    v = __ldg(tags + (size_t)b * AD * RR + (size_t)lane * RR
                                   + (size_t)x * RES + y);

                float s1 = v, s2 = v * v;
                #pragma unroll
                for (int o = 16; o > 0; o >>= 1) {
                    s1 += __shfl_down_sync(FULL, s1, o);
                    s2 += __shfl_down_sync(FULL, s2, o);
                }

                if (lane < AD) atomicAdd(&g_psum[pt * AD + lane], v);  // RED
                if (lane == 0) {
                    // sum_{d1,d2}(t_d1 - t_d2)^2 = 2*D*S2 - 2*S1^2
                    atomicAdd(&g_sqp[pt], 2.0f * (float)AD * s2 - 2.0f * s1 * s1);
                    atomicAdd(&g_cnt[pt], 1.0f);
                }
            }
        }
    }

    // ---------------- arrival: last CTA of this image finalizes ------------
    __shared__ int is_last;
    if (tid == 0) {
        __threadfence();                             // publish REDs
        is_last = (atomicAdd(&g_done[b], 1u) == CPI - 1) ? 1 : 0;
        if (is_last) {
            g_done[b] = 0u;                          // reset for next replay
            __threadfence();                         // acquire
        }
    }
    __syncthreads();
    if (!is_last) return;

    // ---------------- Phase B: thin finalize (512 threads) -----------------
    __shared__ float rcnt[MP];
    __shared__ float pv[MP];
    __shared__ float sqp_s[MP];
    __shared__ float mean_s[MP][AD];
    __shared__ float ntags_s;
    __shared__ float push_acc;

    if (tid == 0) push_acc = 0.0f;

    float psv = 0.0f;
    if (tid < MP * AD) psv = g_psum[b * MP * AD + tid];
    if (tid < MP) {
        const float c = g_cnt[b * MP + tid];
        sqp_s[tid] = g_sqp[b * MP + tid];
        pv[tid]    = (c > 0.0f) ? 1.0f : 0.0f;
        rcnt[tid]  = 1.0f / fmaxf(c, 1.0f);
    }
    __syncthreads();

    if (tid < MP * AD)
        mean_s[tid / AD][tid % AD] = psv * rcnt[tid / AD];

    // n_tags + pull on warp 0
    if (tid < 32) {
        float nt = 0.0f, pl = 0.0f;
        if (tid < MP) {
            nt = pv[tid];
            pl = pv[tid] * sqp_s[tid] * rcnt[tid] * (1.0f / (float)(AD * AD));
        }
        #pragma unroll
        for (int o = 16; o > 0; o >>= 1) {
            nt += __shfl_down_sync(FULL, nt, o);
            pl += __shfl_down_sync(FULL, pl, o);
        }
        if (tid == 0) {
            ntags_s = nt;
            out[BATCH + b] = pl / fmaxf(nt, 1.0f);   // pull[16]
        }
    }

    // zero this image's accumulators for the next graph replay
    if (tid < MP * AD) g_psum[b * MP * AD + tid] = 0.0f;
    if (tid < MP) { g_sqp[b * MP + tid] = 0.0f; g_cnt[b * MP + tid] = 0.0f; }
    __syncthreads();

    // push: 435 unordered pairs, closed-form triangular decode, 17 EX2 each
    float acc = 0.0f;
    if (tid < NPAIR) {
        const int p = tid;
        float disc = (float)((2 * MP - 1) * (2 * MP - 1)) - 8.0f * (float)p;
        int m1 = (int)floorf(((float)(2 * MP - 1) - sqrtf(disc)) * 0.5f);
        if ((m1 + 1) * (2 * MP - 2 - m1) / 2 <= p) m1++;
        if (m1 * (2 * MP - 1 - m1) / 2 > p)        m1--;
        const int m2 = m1 + 1 + (p - m1 * (2 * MP - 1 - m1) / 2);

        if (pv[m1] * pv[m2] != 0.0f) {
            float s = 0.0f;
            #pragma unroll
            for (int d = 0; d < AD; d++) {
                float df = mean_s[m1][d] - mean_s[m2][d];
                s += __expf(-df * df);
            }
            acc = s * (1.0f / (float)AD);
        }
    }
    #pragma unroll
    for (int o = 16; o > 0; o >>= 1)
        acc += __shfl_down_sync(FULL, acc, o);
    if ((tid & 31) == 0 && tid < NPAIR) atomicAdd(&push_acc, acc);
    __syncthreads();

    if (tid == 0) {
        const float nt = ntags_s;
        const float denom = fmaxf(nt, 1.0f);
        // ordered off-diag = 2 * unordered; diagonal sum = nt (exp(0)=1)
        out[b] = (nt >= 2.0f) ? ((2.0f * push_acc + nt) / (denom * denom)) : 0.0f;
    }
}

extern "C" void kernel_launch(void* const* d_in, const int* in_sizes, int n_in,
                              void* d_out, int out_size)
{
    const float* tags   = (const float*)d_in[0];
    const int*   joints = (const int*)d_in[1];
    float*       out    = (float*)d_out;

    ae_fused_kernel<<<BATCH * CPI, 512>>>(tags, joints, out);
}